// round 1
// baseline (speedup 1.0000x reference)
#include <cuda_runtime.h>
#include <cuda_bf16.h>

// Problem constants
#define B_    8
#define C_IN  64
#define C_OUT 128
#define H_IN  256
#define W_IN  256
#define H_OUT 128
#define W_OUT 128
#define M_MAP 800000
#define V_SEG 200000
#define N_PTS 50000

#define CICHUNK 8      // input-channel chunk held in smem
#define WOT 32         // wo tile per block

// Scratch: conv output in NHWC-flat layout [B*H_OUT*W_OUT, C_OUT] (67 MB)
__device__ __align__(256) float g_y[(size_t)B_ * H_OUT * W_OUT * C_OUT];
// Transposed weights: [ci][k][co] (294 KB) for vectorized smem fills
__device__ __align__(256) float g_wT[C_IN * 9 * C_OUT];

// ---------------------------------------------------------------------------
// Kernel 0: transpose weights (C_OUT,C_IN,3,3) -> [ci][k][co]
// ---------------------------------------------------------------------------
__global__ void wt_transpose_kernel(const float* __restrict__ w) {
    int idx = blockIdx.x * blockDim.x + threadIdx.x;
    int total = C_IN * 9 * C_OUT;
    if (idx >= total) return;
    int co = idx % C_OUT;
    int k  = (idx / C_OUT) % 9;
    int ci = idx / (9 * C_OUT);
    g_wT[idx] = w[(co * C_IN + ci) * 9 + k];
}

// ---------------------------------------------------------------------------
// Kernel 1: 3x3 stride-2 pad-1 conv + bias + ReLU, NCHW in -> NHWC-flat out
// Block: 256 threads computes (1 b, 1 ho, 32 wo, 128 co).
// Thread t: co4 = (t&31)*4, wo_l = (t>>5)*4  -> 4 wo x 4 co accumulators.
// ---------------------------------------------------------------------------
__global__ __launch_bounds__(256) void conv_kernel(
    const float* __restrict__ x,
    const float* __restrict__ bias)
{
    __shared__ float x_s[CICHUNK][3][66];
    __shared__ float w_s[CICHUNK][9][C_OUT];

    const int wt = blockIdx.x;    // 0..3
    const int ho = blockIdx.y;    // 0..127
    const int b  = blockIdx.z;    // 0..7
    const int t  = threadIdx.x;
    const int co4  = (t & 31) * 4;
    const int wo_l = (t >> 5) * 4;
    const int wb = wt * WOT;

    float acc[4][4];
    #pragma unroll
    for (int i = 0; i < 4; i++)
        #pragma unroll
        for (int j = 0; j < 4; j++)
            acc[i][j] = 0.0f;

    for (int cc = 0; cc < C_IN; cc += CICHUNK) {
        // --- cooperative load of input tile: [CICHUNK][3 rows][65 cols + pad]
        for (int idx = t; idx < CICHUNK * 3 * 66; idx += 256) {
            int c  = idx % 66;
            int r  = (idx / 66) % 3;
            int ci = idx / (3 * 66);
            int ih = 2 * ho - 1 + r;
            int iw = 2 * wb - 1 + c;
            float v = 0.0f;
            if (c < 65 && ih >= 0 && ih < H_IN && iw >= 0 && iw < W_IN)
                v = x[(((size_t)(b * C_IN + cc + ci)) * H_IN + ih) * W_IN + iw];
            x_s[ci][r][c] = v;
        }
        // --- cooperative load of weight chunk (vectorized, contiguous in g_wT)
        {
            const float4* src = (const float4*)&g_wT[(size_t)cc * 9 * C_OUT];
            float4* dst = (float4*)&w_s[0][0][0];
            for (int idx = t; idx < CICHUNK * 9 * C_OUT / 4; idx += 256)
                dst[idx] = src[idx];
        }
        __syncthreads();

        #pragma unroll
        for (int ci = 0; ci < CICHUNK; ci++) {
            #pragma unroll
            for (int kh = 0; kh < 3; kh++) {
                float xr[9];
                #pragma unroll
                for (int q = 0; q < 9; q++)
                    xr[q] = x_s[ci][kh][2 * wo_l + q];
                #pragma unroll
                for (int kw = 0; kw < 3; kw++) {
                    float4 wv = *(const float4*)&w_s[ci][kh * 3 + kw][co4];
                    #pragma unroll
                    for (int i = 0; i < 4; i++) {
                        float xv = xr[kw + 2 * i];
                        acc[i][0] = fmaf(xv, wv.x, acc[i][0]);
                        acc[i][1] = fmaf(xv, wv.y, acc[i][1]);
                        acc[i][2] = fmaf(xv, wv.z, acc[i][2]);
                        acc[i][3] = fmaf(xv, wv.w, acc[i][3]);
                    }
                }
            }
        }
        __syncthreads();
    }

    // --- epilogue: bias + ReLU, store NHWC-flat (float4 per wo)
    float4 bv = *(const float4*)&bias[co4];
    #pragma unroll
    for (int i = 0; i < 4; i++) {
        int wo = wb + wo_l + i;
        float4 o;
        o.x = fmaxf(acc[i][0] + bv.x, 0.0f);
        o.y = fmaxf(acc[i][1] + bv.y, 0.0f);
        o.z = fmaxf(acc[i][2] + bv.z, 0.0f);
        o.w = fmaxf(acc[i][3] + bv.w, 0.0f);
        size_t pix = ((size_t)(b * H_OUT + ho)) * W_OUT + wo;
        *(float4*)&g_y[pix * C_OUT + co4] = o;
    }
}

// ---------------------------------------------------------------------------
// Kernel 2: fused gather + flattened double segment-max + additive fusion.
// One warp per 3D point. CSR-within-CSR => pixel range for point n is
// [a_ptr[v_ptr[n]], a_ptr[v_ptr[n+1]]). All values >= 0 (post-ReLU), so
// 0-initialized max == reference's isfinite->0 handling at both levels.
// Lane handles channels [lane*4, lane*4+4) as one float4.
// ---------------------------------------------------------------------------
__global__ __launch_bounds__(256) void pool_fuse_kernel(
    const float* __restrict__ x3d,
    const int*   __restrict__ fm_idx,
    const int*   __restrict__ a_ptr,
    const int*   __restrict__ v_ptr,
    float*       __restrict__ out)
{
    int warp = (blockIdx.x * blockDim.x + threadIdx.x) >> 5;
    int lane = threadIdx.x & 31;
    if (warp >= N_PTS) return;

    int v0 = v_ptr[warp];
    int v1 = v_ptr[warp + 1];
    int lo = a_ptr[v0];
    int hi = a_ptr[v1];

    float4 acc = make_float4(0.0f, 0.0f, 0.0f, 0.0f);
    int i = lo;
    // 4-wide unroll for MLP on the dependent idx->row loads
    for (; i + 4 <= hi; i += 4) {
        int r0 = fm_idx[i + 0];
        int r1 = fm_idx[i + 1];
        int r2 = fm_idx[i + 2];
        int r3 = fm_idx[i + 3];
        float4 y0 = *(const float4*)&g_y[(size_t)r0 * C_OUT + lane * 4];
        float4 y1 = *(const float4*)&g_y[(size_t)r1 * C_OUT + lane * 4];
        float4 y2 = *(const float4*)&g_y[(size_t)r2 * C_OUT + lane * 4];
        float4 y3 = *(const float4*)&g_y[(size_t)r3 * C_OUT + lane * 4];
        acc.x = fmaxf(fmaxf(fmaxf(acc.x, y0.x), fmaxf(y1.x, y2.x)), y3.x);
        acc.y = fmaxf(fmaxf(fmaxf(acc.y, y0.y), fmaxf(y1.y, y2.y)), y3.y);
        acc.z = fmaxf(fmaxf(fmaxf(acc.z, y0.z), fmaxf(y1.z, y2.z)), y3.z);
        acc.w = fmaxf(fmaxf(fmaxf(acc.w, y0.w), fmaxf(y1.w, y2.w)), y3.w);
    }
    for (; i < hi; i++) {
        int r = fm_idx[i];
        float4 yv = *(const float4*)&g_y[(size_t)r * C_OUT + lane * 4];
        acc.x = fmaxf(acc.x, yv.x);
        acc.y = fmaxf(acc.y, yv.y);
        acc.z = fmaxf(acc.z, yv.z);
        acc.w = fmaxf(acc.w, yv.w);
    }

    float4 xv = *(const float4*)&x3d[(size_t)warp * C_OUT + lane * 4];
    float4 o = make_float4(acc.x + xv.x, acc.y + xv.y, acc.z + xv.z, acc.w + xv.w);
    *(float4*)&out[(size_t)warp * C_OUT + lane * 4] = o;
}

// ---------------------------------------------------------------------------
// Launch
// Input order (metadata): x, w, b, x_3d, fm_idx, a_ptr, v_ptr
// ---------------------------------------------------------------------------
extern "C" void kernel_launch(void* const* d_in, const int* in_sizes, int n_in,
                              void* d_out, int out_size)
{
    const float* x      = (const float*)d_in[0];
    const float* w      = (const float*)d_in[1];
    const float* bias   = (const float*)d_in[2];
    const float* x3d    = (const float*)d_in[3];
    const int*   fm_idx = (const int*)d_in[4];
    const int*   a_ptr  = (const int*)d_in[5];
    const int*   v_ptr  = (const int*)d_in[6];
    float* out = (float*)d_out;

    // K0: weight transpose (73728 elems)
    wt_transpose_kernel<<<(C_IN * 9 * C_OUT + 255) / 256, 256>>>(w);

    // K1: conv + bias + relu -> g_y (NHWC-flat)
    dim3 cgrid(W_OUT / WOT, H_OUT, B_);
    conv_kernel<<<cgrid, 256>>>(x, bias);

    // K2: fused gather + double segment-max + add
    int nblocks = (N_PTS + 7) / 8;   // 8 warps per 256-thread block
    pool_fuse_kernel<<<nblocks, 256>>>(x3d, fm_idx, a_ptr, v_ptr, out);
}